// round 8
// baseline (speedup 1.0000x reference)
#include <cuda_runtime.h>
#include <cuda_fp16.h>
#include <cstdint>
#include <cstddef>

// ---------------- problem dims ----------------
#define BB   32
#define CIN  128
#define HH   64
#define WW   64
#define COUT 256
#define OH_  62
#define OW_  62
#define NPIX (BB * HH * WW)      // 131072 flat pixels
#define PADR 512                 // zero pad rows past the image
#define XROWS (NPIX + PADR)

// scratch (device globals: allocation-free rule)
__device__ __align__(128) __half g_x[(size_t)XROWS * CIN];   // [pixel][c] fp16 (NHWC)
__device__ __align__(128) __half g_w[9 * COUT * CIN];        // [shift][n][c] fp16 (+-1)

// ---------------- helpers ----------------
__device__ __forceinline__ uint32_t smem_u32(const void* p) {
    uint32_t a;
    asm("{ .reg .u64 t; cvta.to.shared.u64 t, %1; cvt.u32.u64 %0, t; }" : "=r"(a) : "l"(p));
    return a;
}
__device__ __forceinline__ uint32_t swz(uint32_t off) {       // SW128 on 128B rows
    return off ^ ((off >> 3) & 0x70);
}

#define CP_ASYNC16(dst, src) \
    asm volatile("cp.async.cg.shared.global [%0], [%1], 16;" :: "r"(dst), "l"(src) : "memory")
#define CP_COMMIT() asm volatile("cp.async.commit_group;" ::: "memory")
#define CP_WAIT(n)  asm volatile("cp.async.wait_group %0;" :: "n"(n) : "memory")

#define LDSM_X4(r0, r1, r2, r3, addr) \
    asm volatile("ldmatrix.sync.aligned.m8n8.x4.shared.b16 {%0,%1,%2,%3}, [%4];" \
        : "=r"(r0), "=r"(r1), "=r"(r2), "=r"(r3) : "r"(addr))

#define MMA16816(d, a, bb, c) \
    asm volatile("mma.sync.aligned.m16n8k16.row.col.f32.f16.f16.f32 " \
        "{%0,%1,%2,%3}, {%4,%5,%6,%7}, {%8,%9}, {%10,%11,%12,%13};" \
        : "=f"((d)[0]), "=f"((d)[1]), "=f"((d)[2]), "=f"((d)[3]) \
        : "r"((a)[0]), "r"((a)[1]), "r"((a)[2]), "r"((a)[3]), \
          "r"((bb)[0]), "r"((bb)[1]), \
          "f"((c)[0]), "f"((c)[1]), "f"((c)[2]), "f"((c)[3]))

// ---------------- prep kernels ----------------
__global__ void zero_pad_kernel() {
    int idx = blockIdx.x * 256 + threadIdx.x;
    if (idx < PADR * CIN) g_x[(size_t)NPIX * CIN + idx] = __float2half(0.0f);
}

// NCHW f32 -> [pixel][c] fp16 via smem transpose. One block per (b, h) row.
__global__ void __launch_bounds__(256) xpose_kernel(const float* __restrict__ x) {
    __shared__ float s[128 * 65];
    int bid = blockIdx.x;
    int b = bid >> 6, hh = bid & 63;
    int tid = threadIdx.x;
    const float4* src = (const float4*)(x + (size_t)b * (CIN * HH * WW)
                                          + (size_t)hh * WW);
    #pragma unroll
    for (int i = tid; i < CIN * (WW / 4); i += 256) {   // float4 loads
        int c = i >> 4, w4 = i & 15;
        float4 v = src[(size_t)c * (HH * WW / 4) + w4];
        s[c * 65 + w4 * 4 + 0] = v.x;
        s[c * 65 + w4 * 4 + 1] = v.y;
        s[c * 65 + w4 * 4 + 2] = v.z;
        s[c * 65 + w4 * 4 + 3] = v.w;
    }
    __syncthreads();
    __half2* dst = (__half2*)(g_x + (size_t)bid * WW * CIN);
    #pragma unroll
    for (int i = tid; i < (CIN / 2) * WW; i += 256) {
        int c2 = (i & 63) * 2, w = i >> 6;
        dst[w * (CIN / 2) + (c2 >> 1)] =
            __floats2half2_rn(s[c2 * 65 + w], s[(c2 + 1) * 65 + w]);
    }
}

// W (256,128,3,3) f32 -> g_w[shift][n][c] fp16 with value 1-2W (exact +-1)
__global__ void wprep_kernel(const float* __restrict__ W) {
    int i = blockIdx.x * 256 + threadIdx.x;
    if (i < 9 * COUT * CIN) {
        int c = i & 127;
        int n = (i >> 7) & 255;
        int s = i >> 15;                       // kh*3+kw
        float v = 1.0f - 2.0f * W[(size_t)(n * CIN + c) * 9 + s];
        g_w[i] = __float2half_rn(v);
    }
}

// ---------------- GEMM kernel (persistent, mma.sync) ----------------
// C[M=131072, N=256] = A[M,K=1152] * W[N,K]^T
// PERSISTENT: grid=296 (2 CTAs/SM); each CTA loops over ~7 tiles with the
// cp.async pipeline running continuously across tile boundaries.
// CTA tile: M=128, N=128. 8 warps, warp grid 2(M) x 4(N), warp tile 64x32.
// Stage: A 16KB + B 16KB = 32KB, 3 stages = 96KB/CTA.

static constexpr int NS = 3;
static constexpr int A_BYTES = 128 * 128;                // 16KB
static constexpr int STAGE_BYTES = A_BYTES + 128 * 128;  // 32KB
static constexpr int SMEM_BYTES = NS * STAGE_BYTES + 1024;
static constexpr int NCHUNK = 18;
static constexpr int NTHR = 256;
static constexpr int NTILE = (NPIX / 128) * 2;           // 2048
static constexpr int PGRID = 296;                        // 2 x 148 SMs

__device__ __forceinline__ void load_chunk(int chunk, uint32_t sb, int pbase,
                                           int nbase, int tid) {
    int s = chunk >> 1, h = chunk & 1;
    int kh = s / 3, kw = s - kh * 3;
    int pix0 = pbase + kh * WW + kw;
    const char* srcA = (const char*)g_x + (size_t)pix0 * (CIN * 2) + h * 128;
    const char* srcB = (const char*)g_w
        + (size_t)(s * COUT + nbase) * (CIN * 2) + h * 128;
    #pragma unroll
    for (int i = 0; i < 4; i++) {                // A: 128 rows x 128B = 1024 x 16B
        int u = i * NTHR + tid;
        int row = u >> 3, col = (u & 7) << 4;
        CP_ASYNC16(sb + swz((uint32_t)(row * 128 + col)),
                   srcA + (size_t)row * 256 + col);
    }
    #pragma unroll
    for (int i = 0; i < 4; i++) {                // B: 128 rows x 128B
        int u = i * NTHR + tid;
        int row = u >> 3, col = (u & 7) << 4;
        CP_ASYNC16(sb + A_BYTES + swz((uint32_t)(row * 128 + col)),
                   srcB + (size_t)row * 256 + col);
    }
}

__global__ void __launch_bounds__(NTHR, 2) gemm_kernel(float* __restrict__ out) {
    extern __shared__ char dynsmem[];
    uint32_t sm0 = (smem_u32(dynsmem) + 1023u) & ~1023u;

    int tid = threadIdx.x;
    int lane = tid & 31, wid = tid >> 5;
    int warp_m = wid & 1;            // 0..1  (64-row slices)
    int warp_n = wid >> 1;           // 0..3  (32-col slices)
    int bid = blockIdx.x;

    float acc[4][4][4];              // 64 regs
    #pragma unroll
    for (int i = 0; i < 4; i++)
        #pragma unroll
        for (int j = 0; j < 4; j++)
            #pragma unroll
            for (int k = 0; k < 4; k++) acc[i][j][k] = 0.0f;

    int lmat = lane >> 3;            // ldmatrix matrix index 0..3
    int lrow = lane & 7;             // row within 8x8
    int a_mrow = warp_m * 64 + (lmat & 1) * 8 + lrow;    // + mi*16
    int a_koff = (lmat >> 1) * 16;                       // + kk*32
    int b_nrow = warp_n * 32 + (lmat >> 1) * 8 + lrow;   // + nj2*16
    int b_koff = (lmat & 1) * 16;                        // + kk*32

    // prologue: first tile's chunks 0,1 into stages 0,1
    {
        int pb0 = (bid >> 1) * 128, nb0 = (bid & 1) * 128;
        load_chunk(0, sm0, pb0, nb0, tid);                 CP_COMMIT();
        load_chunk(1, sm0 + STAGE_BYTES, pb0, nb0, tid);   CP_COMMIT();
    }

    int stage = 0;                   // stage of the chunk being consumed

    for (int t = bid; t < NTILE; t += PGRID) {
        int pbase = (t >> 1) * 128;
        int nbase = (t & 1) * 128;

        for (int k = 0; k < NCHUNK; k++) {
            CP_WAIT(1);
            __syncthreads();

            // continuous lookahead: chunk k+2 of this tile, or k+2-18 of my
            // next tile (dummy clamped to my first tile past the end so the
            // commit-group count stays uniform).
            {
                int k2 = k + 2, t2 = t;
                if (k2 >= NCHUNK) { k2 -= NCHUNK; t2 = t + PGRID; }
                if (t2 >= NTILE) t2 = bid;       // dummy, never consumed
                int st2 = stage + 2; if (st2 >= NS) st2 -= NS;
                load_chunk(k2, sm0 + st2 * STAGE_BYTES,
                           (t2 >> 1) * 128, (t2 & 1) * 128, tid);
                CP_COMMIT();
            }

            uint32_t sA = sm0 + stage * STAGE_BYTES;
            uint32_t sB = sA + A_BYTES;

            #pragma unroll
            for (int kk = 0; kk < 4; kk++) {     // 4 x k16 within 64 channels
                uint32_t a[4][4];
                uint32_t b[4][2];
                #pragma unroll
                for (int mi = 0; mi < 4; mi++)
                    LDSM_X4(a[mi][0], a[mi][1], a[mi][2], a[mi][3],
                            sA + swz((uint32_t)((a_mrow + mi * 16) * 128
                                                + kk * 32 + a_koff)));
                #pragma unroll
                for (int nj2 = 0; nj2 < 2; nj2++) {
                    uint32_t r0, r1, r2, r3;
                    LDSM_X4(r0, r1, r2, r3,
                            sB + swz((uint32_t)((b_nrow + nj2 * 16) * 128
                                                + kk * 32 + b_koff)));
                    b[nj2 * 2 + 0][0] = r0; b[nj2 * 2 + 0][1] = r1;
                    b[nj2 * 2 + 1][0] = r2; b[nj2 * 2 + 1][1] = r3;
                }
                #pragma unroll
                for (int mi = 0; mi < 4; mi++)
                    #pragma unroll
                    for (int nj = 0; nj < 4; nj++)
                        MMA16816(acc[mi][nj], a[mi], b[nj], acc[mi][nj]);
            }

            stage = (stage + 1 == NS) ? 0 : stage + 1;
        }

        // ---------------- per-tile epilogue (registers only) ----------------
        // acc[mi][nj][q]: row = warp_m*64 + mi*16 + lane/4 + 8*(q>=2)
        //                 col = nbase + warp_n*32 + nj*8 + (lane%4)*2 + (q&1)
        int rbase = warp_m * 64 + (lane >> 2);
        int cbase = nbase + warp_n * 32 + (lane & 3) * 2;
        #pragma unroll
        for (int mi = 0; mi < 4; mi++) {
            #pragma unroll
            for (int half = 0; half < 2; half++) {
                int p = pbase + rbase + mi * 16 + half * 8;   // flat pixel
                int wo = p & 63, oh = (p >> 6) & 63, bb = p >> 12;
                if (wo >= OW_ || oh >= OH_) continue;
                float* obase = out + (size_t)bb * COUT * (OH_ * OW_)
                                   + (size_t)oh * OW_ + wo;
                #pragma unroll
                for (int nj = 0; nj < 4; nj++) {
                    int c = cbase + nj * 8;
                    obase[(size_t)c * (OH_ * OW_)]       = acc[mi][nj][half * 2 + 0];
                    obase[(size_t)(c + 1) * (OH_ * OW_)] = acc[mi][nj][half * 2 + 1];
                }
            }
        }
        #pragma unroll
        for (int i = 0; i < 4; i++)
            #pragma unroll
            for (int j = 0; j < 4; j++)
                #pragma unroll
                for (int q = 0; q < 4; q++) acc[i][j][q] = 0.0f;
    }

    CP_WAIT(0);          // drain dummy groups before exit
    __syncthreads();
}

// ---------------- launch ----------------
extern "C" void kernel_launch(void* const* d_in, const int* in_sizes, int n_in,
                              void* d_out, int out_size) {
    const float* x = (const float*)d_in[0];
    const float* w = (const float*)d_in[1];
    if (n_in >= 2 && in_sizes[0] < in_sizes[1]) {   // defensive: x is the big tensor
        x = (const float*)d_in[1];
        w = (const float*)d_in[0];
    }
    float* out = (float*)d_out;

    cudaFuncSetAttribute(gemm_kernel, cudaFuncAttributeMaxDynamicSharedMemorySize, SMEM_BYTES);

    zero_pad_kernel<<<256, 256>>>();
    xpose_kernel<<<BB * HH, 256>>>(x);
    wprep_kernel<<<(9 * COUT * CIN) / 256, 256>>>(w);
    gemm_kernel<<<PGRID, NTHR, SMEM_BYTES>>>(out);
}

// round 9
// speedup vs baseline: 1.0829x; 1.0829x over previous
#include <cuda_runtime.h>
#include <cuda_fp16.h>
#include <cstdint>
#include <cstddef>

// ---------------- problem dims ----------------
#define BB   32
#define CIN  128
#define HH   64
#define WW   64
#define COUT 256
#define OH_  62
#define OW_  62
#define NPIX (BB * HH * WW)      // 131072 flat pixels
#define PADR 512                 // zero pad rows past the image (zero-init .bss)
#define XROWS (NPIX + PADR)

// scratch (device globals: allocation-free rule; zero-initialized by CUDA,
// so the PADR tail of g_x is guaranteed zero without an explicit kernel)
__device__ __align__(128) __half g_x[(size_t)XROWS * CIN];   // [pixel][c] fp16 (NHWC)
__device__ __align__(128) __half g_w[9 * COUT * CIN];        // [shift][n][c] fp16 (+-1)

// ---------------- helpers ----------------
__device__ __forceinline__ uint32_t smem_u32(const void* p) {
    uint32_t a;
    asm("{ .reg .u64 t; cvta.to.shared.u64 t, %1; cvt.u32.u64 %0, t; }" : "=r"(a) : "l"(p));
    return a;
}
__device__ __forceinline__ uint32_t swz(uint32_t off) {       // SW128 on 128B rows
    return off ^ ((off >> 3) & 0x70);
}

#define CP_ASYNC16(dst, src) \
    asm volatile("cp.async.cg.shared.global [%0], [%1], 16;" :: "r"(dst), "l"(src) : "memory")
#define CP_COMMIT() asm volatile("cp.async.commit_group;" ::: "memory")
#define CP_WAIT(n)  asm volatile("cp.async.wait_group %0;" :: "n"(n) : "memory")

#define LDSM_X4(r0, r1, r2, r3, addr) \
    asm volatile("ldmatrix.sync.aligned.m8n8.x4.shared.b16 {%0,%1,%2,%3}, [%4];" \
        : "=r"(r0), "=r"(r1), "=r"(r2), "=r"(r3) : "r"(addr))

#define MMA16816(d, a, bb, c) \
    asm volatile("mma.sync.aligned.m16n8k16.row.col.f32.f16.f16.f32 " \
        "{%0,%1,%2,%3}, {%4,%5,%6,%7}, {%8,%9}, {%10,%11,%12,%13};" \
        : "=f"((d)[0]), "=f"((d)[1]), "=f"((d)[2]), "=f"((d)[3]) \
        : "r"((a)[0]), "r"((a)[1]), "r"((a)[2]), "r"((a)[3]), \
          "r"((bb)[0]), "r"((bb)[1]), \
          "f"((c)[0]), "f"((c)[1]), "f"((c)[2]), "f"((c)[3]))

// ---------------- prep kernels ----------------

// NCHW f32 -> [pixel][c] fp16 via smem transpose. One block per (b, h) row.
__global__ void __launch_bounds__(256) xpose_kernel(const float* __restrict__ x) {
    __shared__ float s[128 * 65];
    int bid = blockIdx.x;
    int b = bid >> 6, hh = bid & 63;
    int tid = threadIdx.x;
    const float4* src = (const float4*)(x + (size_t)b * (CIN * HH * WW)
                                          + (size_t)hh * WW);
    #pragma unroll
    for (int i = tid; i < CIN * (WW / 4); i += 256) {   // float4 loads
        int c = i >> 4, w4 = i & 15;
        float4 v = src[(size_t)c * (HH * WW / 4) + w4];
        s[c * 65 + w4 * 4 + 0] = v.x;
        s[c * 65 + w4 * 4 + 1] = v.y;
        s[c * 65 + w4 * 4 + 2] = v.z;
        s[c * 65 + w4 * 4 + 3] = v.w;
    }
    __syncthreads();
    __half2* dst = (__half2*)(g_x + (size_t)bid * WW * CIN);
    #pragma unroll
    for (int i = tid; i < (CIN / 2) * WW; i += 256) {
        int c2 = (i & 63) * 2, w = i >> 6;
        dst[w * (CIN / 2) + (c2 >> 1)] =
            __floats2half2_rn(s[c2 * 65 + w], s[(c2 + 1) * 65 + w]);
    }
}

// W (256,128,3,3) f32 -> g_w[shift][n][c] fp16 with value 1-2W (exact +-1)
__global__ void wprep_kernel(const float* __restrict__ W) {
    int i = blockIdx.x * 256 + threadIdx.x;
    if (i < 9 * COUT * CIN) {
        int c = i & 127;
        int n = (i >> 7) & 255;
        int s = i >> 15;                       // kh*3+kw
        float v = 1.0f - 2.0f * W[(size_t)(n * CIN + c) * 9 + s];
        g_w[i] = __float2half_rn(v);
    }
}

// ---------------- GEMM kernel (mma.sync) ----------------
// C[M=131072, N=256] = A[M,K=1152] * W[N,K]^T
// FOUR independent CTAs per SM (the only axis measured to raise tensor%:
// 1 sync-domain -> 58%, 2 domains -> 67%). CTA tile: M=64, N=128,
// 4 warps (128 thr), warp grid 1x4, warp tile 64x32.
// Stage: A 64x64ch (8KB) + B 128x64ch (16KB) = 24KB, 2 stages = 48KB/CTA.
// 2-stage => consume, sync, then refill the just-freed stage.

static constexpr int NS = 2;
static constexpr int A_BYTES = 64 * 128;                 // 8KB
static constexpr int STAGE_BYTES = A_BYTES + 128 * 128;  // 24KB
static constexpr int SMEM_BYTES = NS * STAGE_BYTES + 1024;
static constexpr int NCHUNK = 18;
static constexpr int NTHR = 128;

__device__ __forceinline__ void load_chunk(int chunk, uint32_t sb, int pbase,
                                           int nbase, int tid) {
    int s = chunk >> 1, h = chunk & 1;
    int kh = s / 3, kw = s - kh * 3;
    int pix0 = pbase + kh * WW + kw;
    const char* srcA = (const char*)g_x + (size_t)pix0 * (CIN * 2) + h * 128;
    const char* srcB = (const char*)g_w
        + (size_t)(s * COUT + nbase) * (CIN * 2) + h * 128;
    #pragma unroll
    for (int i = 0; i < 4; i++) {                // A: 64 rows x 128B = 512 x 16B
        int u = i * NTHR + tid;
        int row = u >> 3, col = (u & 7) << 4;
        CP_ASYNC16(sb + swz((uint32_t)(row * 128 + col)),
                   srcA + (size_t)row * 256 + col);
    }
    #pragma unroll
    for (int i = 0; i < 8; i++) {                // B: 128 rows x 128B = 1024 x 16B
        int u = i * NTHR + tid;
        int row = u >> 3, col = (u & 7) << 4;
        CP_ASYNC16(sb + A_BYTES + swz((uint32_t)(row * 128 + col)),
                   srcB + (size_t)row * 256 + col);
    }
}

__global__ void __launch_bounds__(NTHR, 4) gemm_kernel(float* __restrict__ out) {
    extern __shared__ char dynsmem[];
    uint32_t sm0 = (smem_u32(dynsmem) + 1023u) & ~1023u;

    int tid = threadIdx.x;
    int lane = tid & 31, wid = tid >> 5;
    int warp_n = wid;                // 0..3 (32-col slices); warp_m = 0

    int pbase = (blockIdx.x >> 1) * 64;    // flat pixel base (M tile)
    int nbase = (blockIdx.x & 1) * 128;    // output-channel base (N tile)

    float acc[4][4][4];              // 64 regs
    #pragma unroll
    for (int i = 0; i < 4; i++)
        #pragma unroll
        for (int j = 0; j < 4; j++)
            #pragma unroll
            for (int k = 0; k < 4; k++) acc[i][j][k] = 0.0f;

    // prologue: chunks 0,1 into stages 0,1
    load_chunk(0, sm0, pbase, nbase, tid);                 CP_COMMIT();
    load_chunk(1, sm0 + STAGE_BYTES, pbase, nbase, tid);   CP_COMMIT();

    int lmat = lane >> 3;            // ldmatrix matrix index 0..3
    int lrow = lane & 7;             // row within 8x8
    int a_mrow = (lmat & 1) * 8 + lrow;                  // + mi*16 (M=64)
    int a_koff = (lmat >> 1) * 16;                       // + kk*32
    int b_nrow = warp_n * 32 + (lmat >> 1) * 8 + lrow;   // + nj2*16
    int b_koff = (lmat & 1) * 16;                        // + kk*32

    for (int k = 0; k < NCHUNK; k++) {
        uint32_t sA = sm0 + (k & 1) * STAGE_BYTES;
        uint32_t sB = sA + A_BYTES;

        if (k < NCHUNK - 1) { CP_WAIT(1); }
        else                { CP_WAIT(0); }
        __syncthreads();

        #pragma unroll
        for (int kk = 0; kk < 4; kk++) {         // 4 x k16 within 64 channels
            uint32_t a[4][4];
            uint32_t b[4][2];
            #pragma unroll
            for (int mi = 0; mi < 4; mi++)
                LDSM_X4(a[mi][0], a[mi][1], a[mi][2], a[mi][3],
                        sA + swz((uint32_t)((a_mrow + mi * 16) * 128
                                            + kk * 32 + a_koff)));
            #pragma unroll
            for (int nj2 = 0; nj2 < 2; nj2++) {
                uint32_t r0, r1, r2, r3;
                LDSM_X4(r0, r1, r2, r3,
                        sB + swz((uint32_t)((b_nrow + nj2 * 16) * 128
                                            + kk * 32 + b_koff)));
                b[nj2 * 2 + 0][0] = r0; b[nj2 * 2 + 0][1] = r1;
                b[nj2 * 2 + 1][0] = r2; b[nj2 * 2 + 1][1] = r3;
            }
            #pragma unroll
            for (int mi = 0; mi < 4; mi++)
                #pragma unroll
                for (int nj = 0; nj < 4; nj++)
                    MMA16816(acc[mi][nj], a[mi], b[nj], acc[mi][nj]);
        }

        __syncthreads();                 // stage (k&1) fully consumed
        if (k + 2 < NCHUNK) {            // refill it with chunk k+2
            load_chunk(k + 2, sm0 + (k & 1) * STAGE_BYTES, pbase, nbase, tid);
            CP_COMMIT();
        }
    }

    // ---------------- epilogue ----------------
    // acc[mi][nj][q]: row = mi*16 + lane/4 + 8*(q>=2)
    //                 col = nbase + warp_n*32 + nj*8 + (lane%4)*2 + (q&1)
    int rbase = lane >> 2;
    int cbase = nbase + warp_n * 32 + (lane & 3) * 2;
    #pragma unroll
    for (int mi = 0; mi < 4; mi++) {
        #pragma unroll
        for (int half = 0; half < 2; half++) {
            int p = pbase + rbase + mi * 16 + half * 8;   // flat pixel
            int wo = p & 63, oh = (p >> 6) & 63, bb = p >> 12;
            if (wo >= OW_ || oh >= OH_) continue;
            float* obase = out + (size_t)bb * COUT * (OH_ * OW_)
                               + (size_t)oh * OW_ + wo;
            #pragma unroll
            for (int nj = 0; nj < 4; nj++) {
                int c = cbase + nj * 8;
                obase[(size_t)c * (OH_ * OW_)]       = acc[mi][nj][half * 2 + 0];
                obase[(size_t)(c + 1) * (OH_ * OW_)] = acc[mi][nj][half * 2 + 1];
            }
        }
    }
}

// ---------------- launch ----------------
extern "C" void kernel_launch(void* const* d_in, const int* in_sizes, int n_in,
                              void* d_out, int out_size) {
    const float* x = (const float*)d_in[0];
    const float* w = (const float*)d_in[1];
    if (n_in >= 2 && in_sizes[0] < in_sizes[1]) {   // defensive: x is the big tensor
        x = (const float*)d_in[1];
        w = (const float*)d_in[0];
    }
    float* out = (float*)d_out;

    cudaFuncSetAttribute(gemm_kernel, cudaFuncAttributeMaxDynamicSharedMemorySize, SMEM_BYTES);

    xpose_kernel<<<BB * HH, 256>>>(x);
    wprep_kernel<<<(9 * COUT * CIN) / 256, 256>>>(w);
    gemm_kernel<<<(NPIX / 64) * 2, NTHR, SMEM_BYTES>>>(out);
}